// round 11
// baseline (speedup 1.0000x reference)
#include <cuda_runtime.h>
#include <cuda_fp16.h>

// Problem constants (fixed by the dataset)
#define B_COLS   64            // dense columns
#define N_MAX    50048         // neuron count (50000) rounded up a bit
#define NNZ_MAX  800000

// Scratch: two fp16 ping-pong buffers + CSR row pointer.
// fp16 dense operand halves the dominant L2 gather traffic (the measured
// roofline): 256B -> 128B per edge. Accumulation stays fp32.
__device__ __half2 g_hA[N_MAX * B_COLS / 2];
__device__ __half2 g_hB[N_MAX * B_COLS / 2];
__device__ int     g_row_ptr[N_MAX + 1];

// ---------------------------------------------------------------------------
// Build CSR row_ptr from the sorted `rows` array.
// ---------------------------------------------------------------------------
__global__ void build_row_ptr_kernel(const int* __restrict__ rows, int nnz, int n,
                                     int* __restrict__ row_ptr) {
    int i = blockIdx.x * blockDim.x + threadIdx.x;
    if (i >= nnz) return;
    int r = rows[i];
    int rprev = (i == 0) ? -1 : rows[i - 1];
    for (int rr = rprev + 1; rr <= r; rr++) row_ptr[rr] = i;
    if (i == nnz - 1) {
        for (int rr = r + 1; rr <= n; rr++) row_ptr[rr] = nnz;
    }
}

// ---------------------------------------------------------------------------
// Convert fp32 [N,64] -> half2 buffer (pairwise).
// ---------------------------------------------------------------------------
__global__ void f2h_kernel(const float* __restrict__ in, __half2* __restrict__ out,
                           int n2) {
    int i = blockIdx.x * blockDim.x + threadIdx.x;
    if (i < n2) {
        float2 f = reinterpret_cast<const float2*>(in)[i];
        out[i] = __floats2half2_rn(f.x, f.y);
    }
}

// ---------------------------------------------------------------------------
// CSR SpMM with fp16 dense operand:
//   out[r,:] = sum_e vals[e] * x[cols[e],:]  (+ bias[r])
// One warp per row (grid-stride). Lane l owns dense cols {2l,2l+1} as ONE
// __half2 (4B) -> the per-edge gather is a single 128B, single-wavefront
// LDG.32. fp32 accumulators. Intermediate layers store half2; the final SpMM
// writes fp32 to d_out.
//
// Operating point proven over R2-R8: 32-reg cap, occ ~100%, TLP hides L2
// latency; 8 edges in flight per iteration.
// ---------------------------------------------------------------------------
template <bool HAS_BIAS, bool OUT_FP32>
__global__ void __launch_bounds__(256, 8)
spmm_h_kernel(const float* __restrict__ vals, const int* __restrict__ cols,
              const int* __restrict__ row_ptr, const __half2* __restrict__ xin,
              const float* __restrict__ bias, void* __restrict__ out, int n) {
    const int lane   = threadIdx.x & 31;
    const int warpId = (blockIdx.x * blockDim.x + threadIdx.x) >> 5;
    const int nWarps = (gridDim.x * blockDim.x) >> 5;

    const __half2* __restrict__ xl = xin + lane;   // lane-offset base (32 half2 per row)

    for (int row = warpId; row < n; row += nWarps) {
        int s = row_ptr[row];
        int e = row_ptr[row + 1];

        float accx = 0.0f, accy = 0.0f;

        int k = s;
        // Peel to 4-edge alignment so float4/int4 metadata loads are 16B aligned.
        while (k < e && (k & 3)) {
            float v = vals[k];
            int   c = cols[k];
            float2 a = __half22float2(xl[c * 32]);
            accx = fmaf(v, a.x, accx); accy = fmaf(v, a.y, accy);
            k++;
        }

        // Main body: 8 edges/iter — 2 float4 + 2 int4 uniform metadata loads,
        // 8 independent single-wavefront 128B gathers in flight.
        for (; k + 8 <= e; k += 8) {
            float4 v0 = *reinterpret_cast<const float4*>(vals + k);
            float4 v1 = *reinterpret_cast<const float4*>(vals + k + 4);
            int4   c0 = *reinterpret_cast<const int4*>(cols + k);
            int4   c1 = *reinterpret_cast<const int4*>(cols + k + 4);
            __half2 h0 = xl[c0.x * 32];
            __half2 h1 = xl[c0.y * 32];
            __half2 h2 = xl[c0.z * 32];
            __half2 h3 = xl[c0.w * 32];
            __half2 h4 = xl[c1.x * 32];
            __half2 h5 = xl[c1.y * 32];
            __half2 h6 = xl[c1.z * 32];
            __half2 h7 = xl[c1.w * 32];
            float2 a0 = __half22float2(h0);
            float2 a1 = __half22float2(h1);
            float2 a2 = __half22float2(h2);
            float2 a3 = __half22float2(h3);
            float2 a4 = __half22float2(h4);
            float2 a5 = __half22float2(h5);
            float2 a6 = __half22float2(h6);
            float2 a7 = __half22float2(h7);
            accx = fmaf(v0.x, a0.x, accx); accy = fmaf(v0.x, a0.y, accy);
            accx = fmaf(v0.y, a1.x, accx); accy = fmaf(v0.y, a1.y, accy);
            accx = fmaf(v0.z, a2.x, accx); accy = fmaf(v0.z, a2.y, accy);
            accx = fmaf(v0.w, a3.x, accx); accy = fmaf(v0.w, a3.y, accy);
            accx = fmaf(v1.x, a4.x, accx); accy = fmaf(v1.x, a4.y, accy);
            accx = fmaf(v1.y, a5.x, accx); accy = fmaf(v1.y, a5.y, accy);
            accx = fmaf(v1.z, a6.x, accx); accy = fmaf(v1.z, a6.y, accy);
            accx = fmaf(v1.w, a7.x, accx); accy = fmaf(v1.w, a7.y, accy);
        }

        // 4-edge group
        for (; k + 4 <= e; k += 4) {
            float4 v0 = *reinterpret_cast<const float4*>(vals + k);
            int4   c0 = *reinterpret_cast<const int4*>(cols + k);
            float2 a0 = __half22float2(xl[c0.x * 32]);
            float2 a1 = __half22float2(xl[c0.y * 32]);
            float2 a2 = __half22float2(xl[c0.z * 32]);
            float2 a3 = __half22float2(xl[c0.w * 32]);
            accx = fmaf(v0.x, a0.x, accx); accy = fmaf(v0.x, a0.y, accy);
            accx = fmaf(v0.y, a1.x, accx); accy = fmaf(v0.y, a1.y, accy);
            accx = fmaf(v0.z, a2.x, accx); accy = fmaf(v0.z, a2.y, accy);
            accx = fmaf(v0.w, a3.x, accx); accy = fmaf(v0.w, a3.y, accy);
        }

        // Scalar tail
        for (; k < e; k++) {
            float v = vals[k];
            int   c = cols[k];
            float2 a = __half22float2(xl[c * 32]);
            accx = fmaf(v, a.x, accx); accy = fmaf(v, a.y, accy);
        }

        if (HAS_BIAS) {
            float b = bias[row];
            accx += b; accy += b;
        }
        if (OUT_FP32) {
            float2 r; r.x = accx; r.y = accy;
            reinterpret_cast<float2*>(out)[row * 32 + lane] = r;
        } else {
            reinterpret_cast<__half2*>(out)[row * 32 + lane] =
                __floats2half2_rn(accx, accy);
        }
    }
}

extern "C" void kernel_launch(void* const* d_in, const int* in_sizes, int n_in,
                              void* d_out, int out_size) {
    const float* x        = (const float*)d_in[0];   // [N, 64]
    const float* adj_vals = (const float*)d_in[1];   // [NNZ]
    const float* w_vals   = (const float*)d_in[2];   // [NNZ]
    const float* bias     = (const float*)d_in[3];   // [N]
    const int*   rows     = (const int*)d_in[4];     // [NNZ] sorted
    const int*   cols     = (const int*)d_in[5];     // [NNZ]
    // n_layers (d_in[6]) lives on device; the problem fixes it at 3.

    const int N   = in_sizes[0] / B_COLS;
    const int NNZ = in_sizes[1];

    __half2* hA = nullptr; __half2* hB = nullptr; int* row_ptr = nullptr;
    cudaGetSymbolAddress((void**)&hA, g_hA);
    cudaGetSymbolAddress((void**)&hB, g_hB);
    cudaGetSymbolAddress((void**)&row_ptr, g_row_ptr);

    float* outp = (float*)d_out;

    // 1) row_ptr
    {
        int threads = 256;
        int blocks = (NNZ + threads - 1) / threads;
        build_row_ptr_kernel<<<blocks, threads>>>(rows, NNZ, N, row_ptr);
    }

    // 2) x -> fp16
    {
        int n2 = N * (B_COLS / 2);
        int threads = 256;
        int blocks = (n2 + threads - 1) / threads;
        f2h_kernel<<<blocks, threads>>>(x, hA, n2);
    }

    // 3) three layers, two SpMMs each; final SpMM writes fp32 to d_out.
    const int threads = 256;
    const int blocks  = 1184;   // one resident wave, grid-stride over rows

    // layer 1
    spmm_h_kernel<false, false><<<blocks, threads>>>(w_vals,   cols, row_ptr, hA, nullptr, hB, N);
    spmm_h_kernel<true,  false><<<blocks, threads>>>(adj_vals, cols, row_ptr, hB, bias,    hA, N);
    // layer 2
    spmm_h_kernel<false, false><<<blocks, threads>>>(w_vals,   cols, row_ptr, hA, nullptr, hB, N);
    spmm_h_kernel<true,  false><<<blocks, threads>>>(adj_vals, cols, row_ptr, hB, bias,    hA, N);
    // layer 3
    spmm_h_kernel<false, false><<<blocks, threads>>>(w_vals,   cols, row_ptr, hA, nullptr, hB, N);
    spmm_h_kernel<true,  true ><<<blocks, threads>>>(adj_vals, cols, row_ptr, hB, bias,    outp, N);
}

// round 12
// speedup vs baseline: 1.0112x; 1.0112x over previous
#include <cuda_runtime.h>

// Problem constants (fixed by the dataset)
#define B_COLS    64           // dense columns
#define N_MAX     50048        // neuron count (50000) rounded up
#define NNZ_MAX   800000
// Padded edge capacity: roundup8(NNZ) + 8*N  (pstart construction below)
#define PAD_MAX   (NNZ_MAX + 8 * N_MAX + 64)

// Scratch (no allocation allowed)
__device__ float g_bufX[N_MAX * B_COLS];
__device__ float g_bufY[N_MAX * B_COLS];
__device__ int   g_row_ptr[N_MAX + 1];
__device__ float g_wp[PAD_MAX];    // padded w_vals
__device__ float g_ap[PAD_MAX];    // padded adj_vals
__device__ int   g_cp[PAD_MAX];    // padded cols (premultiplied by 32 = float2 row stride)

// ---------------------------------------------------------------------------
// Build CSR row_ptr from the sorted `rows` array.
// ---------------------------------------------------------------------------
__global__ void build_row_ptr_kernel(const int* __restrict__ rows, int nnz, int n,
                                     int* __restrict__ row_ptr) {
    int i = blockIdx.x * blockDim.x + threadIdx.x;
    if (i >= nnz) return;
    int r = rows[i];
    int rprev = (i == 0) ? -1 : rows[i - 1];
    for (int rr = rprev + 1; rr <= r; rr++) row_ptr[rr] = i;
    if (i == nnz - 1) {
        for (int rr = r + 1; rr <= n; rr++) row_ptr[rr] = nnz;
    }
}

// Zero-fill the padded arrays (val=0 edges pointing at col 0 contribute 0).
__global__ void zero_pad_kernel(float* __restrict__ wp, float* __restrict__ ap,
                                int* __restrict__ cp, int total) {
    int i = blockIdx.x * blockDim.x + threadIdx.x;
    if (i < total) { wp[i] = 0.0f; ap[i] = 0.0f; cp[i] = 0; }
}

// Scatter edges into the padded 8-aligned layout.
// pstart(row) = roundup8(row_ptr[row]) + 8*row  (8-aligned; capacity >= len).
__global__ void pack_kernel(const float* __restrict__ w_vals,
                            const float* __restrict__ adj_vals,
                            const int* __restrict__ rows,
                            const int* __restrict__ cols,
                            const int* __restrict__ row_ptr,
                            float* __restrict__ wp, float* __restrict__ ap,
                            int* __restrict__ cp, int nnz) {
    int i = blockIdx.x * blockDim.x + threadIdx.x;
    if (i >= nnz) return;
    int r = rows[i];
    int s = row_ptr[r];
    int dst = ((s + 7) & ~7) + 8 * r + (i - s);
    wp[dst] = w_vals[i];
    ap[dst] = adj_vals[i];
    cp[dst] = cols[i] * 32;          // float2 index premultiplied
}

// ---------------------------------------------------------------------------
// Padded CSR SpMM: out[r,:] = sum_e vals[e] * x[cols[e],:]  (+ bias[r])
// One warp per row (grid-stride). Lane l owns dense cols {2l,2l+1} (float2).
// The padded layout makes every row an exact multiple of 8 edges starting at
// an 8-aligned offset: the kernel body is ONLY the vectorized 8-edge loop —
// no peel, no 4-group, no scalar tail, no alignment branches. This attacks
// the measured bottleneck (issue=56%, ~18 instr/edge -> ~6).
// ---------------------------------------------------------------------------
template <bool HAS_BIAS>
__global__ void __launch_bounds__(256, 8)
spmm_pad_kernel(const float* __restrict__ vals, const int* __restrict__ colsx32,
                const int* __restrict__ row_ptr, const float* __restrict__ xin,
                const float* __restrict__ bias, float* __restrict__ out, int n) {
    const int lane   = threadIdx.x & 31;
    const int warpId = (blockIdx.x * blockDim.x + threadIdx.x) >> 5;
    const int nWarps = (gridDim.x * blockDim.x) >> 5;

    const float2* __restrict__ x2 = reinterpret_cast<const float2*>(xin) + lane;

    for (int row = warpId; row < n; row += nWarps) {
        int s0 = row_ptr[row];
        int e0 = row_ptr[row + 1];
        int k  = ((s0 + 7) & ~7) + 8 * row;           // padded, 8-aligned start
        int e  = k + ((e0 - s0 + 7) & ~7);            // padded end (multiple of 8)

        float accx = 0.0f, accy = 0.0f;

        for (; k < e; k += 8) {
            float4 v0 = *reinterpret_cast<const float4*>(vals + k);
            float4 v1 = *reinterpret_cast<const float4*>(vals + k + 4);
            int4   c0 = *reinterpret_cast<const int4*>(colsx32 + k);
            int4   c1 = *reinterpret_cast<const int4*>(colsx32 + k + 4);
            float2 a0 = x2[c0.x];
            float2 a1 = x2[c0.y];
            float2 a2 = x2[c0.z];
            float2 a3 = x2[c0.w];
            float2 a4 = x2[c1.x];
            float2 a5 = x2[c1.y];
            float2 a6 = x2[c1.z];
            float2 a7 = x2[c1.w];
            accx = fmaf(v0.x, a0.x, accx); accy = fmaf(v0.x, a0.y, accy);
            accx = fmaf(v0.y, a1.x, accx); accy = fmaf(v0.y, a1.y, accy);
            accx = fmaf(v0.z, a2.x, accx); accy = fmaf(v0.z, a2.y, accy);
            accx = fmaf(v0.w, a3.x, accx); accy = fmaf(v0.w, a3.y, accy);
            accx = fmaf(v1.x, a4.x, accx); accy = fmaf(v1.x, a4.y, accy);
            accx = fmaf(v1.y, a5.x, accx); accy = fmaf(v1.y, a5.y, accy);
            accx = fmaf(v1.z, a6.x, accx); accy = fmaf(v1.z, a6.y, accy);
            accx = fmaf(v1.w, a7.x, accx); accy = fmaf(v1.w, a7.y, accy);
        }

        if (HAS_BIAS) {
            float b = bias[row];
            accx += b; accy += b;
        }
        float2 r; r.x = accx; r.y = accy;
        (reinterpret_cast<float2*>(out) + lane)[row * 32] = r;
    }
}

extern "C" void kernel_launch(void* const* d_in, const int* in_sizes, int n_in,
                              void* d_out, int out_size) {
    const float* x        = (const float*)d_in[0];   // [N, 64]
    const float* adj_vals = (const float*)d_in[1];   // [NNZ]
    const float* w_vals   = (const float*)d_in[2];   // [NNZ]
    const float* bias     = (const float*)d_in[3];   // [N]
    const int*   rows     = (const int*)d_in[4];     // [NNZ] sorted
    const int*   cols     = (const int*)d_in[5];     // [NNZ]
    // n_layers (d_in[6]) lives on device; the problem fixes it at 3.

    const int N   = in_sizes[0] / B_COLS;
    const int NNZ = in_sizes[1];
    const int PAD_TOTAL = ((NNZ + 7) & ~7) + 8 * N + 8;

    float* bufX = nullptr; float* bufY = nullptr; int* row_ptr = nullptr;
    float* wp = nullptr; float* ap = nullptr; int* cp = nullptr;
    cudaGetSymbolAddress((void**)&bufX, g_bufX);
    cudaGetSymbolAddress((void**)&bufY, g_bufY);
    cudaGetSymbolAddress((void**)&row_ptr, g_row_ptr);
    cudaGetSymbolAddress((void**)&wp, g_wp);
    cudaGetSymbolAddress((void**)&ap, g_ap);
    cudaGetSymbolAddress((void**)&cp, g_cp);

    float* outp = (float*)d_out;

    // 1) row_ptr
    {
        int threads = 256;
        int blocks = (NNZ + threads - 1) / threads;
        build_row_ptr_kernel<<<blocks, threads>>>(rows, NNZ, N, row_ptr);
    }
    // 2) padded edge format (shared by all six SpMMs)
    {
        int threads = 256;
        int blocksZ = (PAD_TOTAL + threads - 1) / threads;
        zero_pad_kernel<<<blocksZ, threads>>>(wp, ap, cp, PAD_TOTAL);
        int blocksP = (NNZ + threads - 1) / threads;
        pack_kernel<<<blocksP, threads>>>(w_vals, adj_vals, rows, cols, row_ptr,
                                          wp, ap, cp, NNZ);
    }

    // 3) three layers, two SpMMs each; final SpMM writes to d_out.
    const int threads = 256;
    const int blocks  = 1184;   // one resident wave, grid-stride over rows

    // layer 1
    spmm_pad_kernel<false><<<blocks, threads>>>(wp, cp, row_ptr, x,    nullptr, bufY, N);
    spmm_pad_kernel<true ><<<blocks, threads>>>(ap, cp, row_ptr, bufY, bias,    bufX, N);
    // layer 2
    spmm_pad_kernel<false><<<blocks, threads>>>(wp, cp, row_ptr, bufX, nullptr, bufY, N);
    spmm_pad_kernel<true ><<<blocks, threads>>>(ap, cp, row_ptr, bufY, bias,    bufX, N);
    // layer 3
    spmm_pad_kernel<false><<<blocks, threads>>>(wp, cp, row_ptr, bufX, nullptr, bufY, N);
    spmm_pad_kernel<true ><<<blocks, threads>>>(ap, cp, row_ptr, bufY, bias,    outp, N);
}